// round 13
// baseline (speedup 1.0000x reference)
#include <cuda_runtime.h>
#include <cuda_bf16.h>
#include <math.h>
#include <stdint.h>

// ConLoss (NT-Xent): z = normalize(concat(h1,h2)) [8192,512]; sim = z z^T; T=0.5
// loss_i = -2*sim[i,i^4096] + log(sum_{j!=i} exp(2*sim_ij)); out = mean.
// Round 13: 64x64 warp tile (4 warps, 128 thr) -> LDSM/MMA 0.375->0.25 with
// a 255-reg budget (no spills). Upper-triangle symmetry, 2-stage cp.async
// ring, 2 CTAs/SM, fused last-CTA loss.

#define NROWS 8192
#define HALF  4096
#define D     512

#define THREADS 128
#define BT 128                        // tile dim
#define NT (NROWS / BT)               // 64
#define NTILES (NT * (NT + 1) / 2)    // 2080
#define NKC 4                         // k chunks of 128

#define CH_BYTES (BT * 128)           // 16 KB per operand chunk
#define STAGE_BYTES (2 * CH_BYTES)    // 32 KB (A+B)
#define SMEM_TOTAL (2 * STAGE_BYTES)  // 64 KB

// exp(2*sim) = 2^(acc * 2*log2e/256), acc = 256*sim (z scaled by 16)
#define EXP_SCALE 0.0112710550f
#define POS_SCALE 0.0078125f          // 2/256

__device__ __align__(16) uint8_t g_z8[NROWS * D];
__device__ float g_S[NROWS];
__device__ float g_pos[NROWS];
__device__ unsigned int g_cnt = 0;

// ---------------- helpers ----------------
__device__ __forceinline__ uint32_t smem_u32(const void* p) {
    uint32_t a;
    asm("{ .reg .u64 t; cvta.to.shared.u64 t, %1; cvt.u32.u64 %0, t; }" : "=r"(a) : "l"(p));
    return a;
}
__device__ __forceinline__ uint32_t SWZ(uint32_t off) {   // SW128 swizzle
    return off ^ ((off >> 3) & 0x70);
}
__device__ __forceinline__ void cp16(uint32_t dst, const void* src) {
    asm volatile("cp.async.cg.shared.global [%0], [%1], 16;" :: "r"(dst), "l"(src));
}
#define CP_COMMIT() asm volatile("cp.async.commit_group;" ::: "memory")
#define CP_WAIT(n)  asm volatile("cp.async.wait_group %0;" :: "n"(n) : "memory")

__device__ __forceinline__ void ldmx4(uint32_t* r, uint32_t addr) {
    asm volatile("ldmatrix.sync.aligned.m8n8.x4.shared.b16 {%0,%1,%2,%3}, [%4];"
                 : "=r"(r[0]), "=r"(r[1]), "=r"(r[2]), "=r"(r[3]) : "r"(addr));
}
__device__ __forceinline__ void mma_fp8(float* c, const uint32_t* a, const uint32_t* b) {
    asm volatile("mma.sync.aligned.m16n8k32.row.col.f32.e4m3.e4m3.f32 "
                 "{%0,%1,%2,%3}, {%4,%5,%6,%7}, {%8,%9}, {%0,%1,%2,%3};"
                 : "+f"(c[0]), "+f"(c[1]), "+f"(c[2]), "+f"(c[3])
                 : "r"(a[0]), "r"(a[1]), "r"(a[2]), "r"(a[3]), "r"(b[0]), "r"(b[1]));
}
__device__ __forceinline__ float ex2f(float x) {
    float y;
    asm("ex2.approx.f32 %0, %1;" : "=f"(y) : "f"(x));
    return y;
}
__device__ __forceinline__ uint32_t pack_e4m3(float f0, float f1, float f2, float f3) {
    uint16_t lo, hi;
    asm("cvt.rn.satfinite.e4m3x2.f32 %0, %1, %2;" : "=h"(lo) : "f"(f1), "f"(f0));
    asm("cvt.rn.satfinite.e4m3x2.f32 %0, %1, %2;" : "=h"(hi) : "f"(f3), "f"(f2));
    return (uint32_t)lo | ((uint32_t)hi << 16);
}

// ---------------- kernels ----------------
// One warp per row: normalize, scale by 16, write e4m3. Also zeroes g_S.
__global__ void norm_kernel(const float* __restrict__ a, const float* __restrict__ b) {
    int gt = blockIdx.x * blockDim.x + threadIdx.x;
    if (gt < NROWS) g_S[gt] = 0.0f;
    int gw   = gt >> 5;
    int lane = threadIdx.x & 31;
    if (gw >= NROWS) return;
    const float* src = (gw < HALF) ? (a + (size_t)gw * D) : (b + (size_t)(gw - HALF) * D);
    const float4* s4 = (const float4*)src;
    float4 v[4];
    float ss = 0.0f;
#pragma unroll
    for (int l = 0; l < 4; l++) {
        v[l] = s4[lane + l * 32];
        ss += v[l].x * v[l].x + v[l].y * v[l].y + v[l].z * v[l].z + v[l].w * v[l].w;
    }
#pragma unroll
    for (int m = 16; m; m >>= 1) ss += __shfl_xor_sync(0xffffffffu, ss, m);
    float inv = 16.0f / fmaxf(sqrtf(ss), 1e-8f);
    uint32_t* d32 = (uint32_t*)(g_z8 + (size_t)gw * D);
#pragma unroll
    for (int l = 0; l < 4; l++) {
        float4 w = v[l];
        d32[lane + 32 * l] = pack_e4m3(w.x * inv, w.y * inv, w.z * inv, w.w * inv);
    }
}

// One CTA per upper-triangle tile (rt, ct), ct >= rt. 128 thr = 4 warps (2x2),
// warp tile 64x64.
__global__ __launch_bounds__(THREADS, 2) void gemm_kernel(float* __restrict__ out) {
    extern __shared__ __align__(1024) char smem[];
    const uint32_t sb = smem_u32(smem);
    const int tid  = threadIdx.x;
    const int wid  = tid >> 5;
    const int lane = tid & 31;
    const int wm = wid & 1;        // row warp: 64 rows
    const int wn = wid >> 1;       // col warp: 64 cols

    // decode flat tile index -> (rt, ct), ct >= rt
    const int flat = blockIdx.x;
    int rt = (int)((2 * NT + 1 - sqrtf((float)((2 * NT + 1) * (2 * NT + 1) - 8 * flat))) * 0.5f);
    while (rt * (2 * NT + 1 - rt) / 2 > flat) rt--;
    while ((rt + 1) * (2 * NT - rt) / 2 <= flat) rt++;
    const int ct = rt + (flat - rt * (2 * NT + 1 - rt) / 2);
    const int row_base = rt * BT;
    const int col_base = ct * BT;
    const bool diag = (rt == ct);

    const uint4* Z4 = (const uint4*)g_z8;   // 32 uint4 per row

    // hoisted cp.async addressing: 2048 cp16 / 128 thr = 16 each (8 row-steps x A,B)
    const int ld_row = tid >> 3;          // 0..15
    const int ld_g   = tid & 7;
    uint32_t dsw[8];
#pragma unroll
    for (int l = 0; l < 8; l++)
        dsw[l] = SWZ((ld_row + 16 * l) * 128 + ld_g * 16);
    const uint4* as0 = Z4 + (size_t)(row_base + ld_row) * 32 + ld_g;
    const uint4* bs0 = Z4 + (size_t)(col_base + ld_row) * 32 + ld_g;

    // prologue: chunk 0
#pragma unroll
    for (int l = 0; l < 8; l++) {
        cp16(sb + dsw[l], as0 + (size_t)l * 16 * 32);
        cp16(sb + CH_BYTES + dsw[l], bs0 + (size_t)l * 16 * 32);
    }
    CP_COMMIT();

    // ldmatrix lane addressing (XOR-advance along k: k-offsets live in bits 4-6)
    const int a_row0 = wm * 64 + (lane & 15);
    uint32_t a_off[4];
#pragma unroll
    for (int mf = 0; mf < 4; mf++)
        a_off[mf] = SWZ((a_row0 + mf * 16) * 128 + (lane >> 4) * 16);
    const int b_row0 = wn * 64 + (lane & 7) + ((lane & 16) ? 8 : 0);
    uint32_t b_off[4];
#pragma unroll
    for (int q = 0; q < 4; q++)
        b_off[q] = SWZ((b_row0 + q * 16) * 128 + ((lane & 8) ? 16 : 0));

    float c[4][8][4];
#pragma unroll
    for (int mf = 0; mf < 4; mf++)
#pragma unroll
        for (int nf = 0; nf < 8; nf++)
#pragma unroll
            for (int e = 0; e < 4; e++) c[mf][nf][e] = 0.0f;

#pragma unroll
    for (int kc = 0; kc < NKC; kc++) {
        CP_WAIT(0);            // chunk kc resident
        __syncthreads();       // publish + all warps done with the other stage
        if (kc + 1 < NKC) {    // prefetch next chunk into freed stage
            const uint32_t dst = sb + ((kc + 1) & 1) * STAGE_BYTES;
            const uint4* a2 = as0 + (size_t)(kc + 1) * 8;
            const uint4* b2 = bs0 + (size_t)(kc + 1) * 8;
#pragma unroll
            for (int l = 0; l < 8; l++) {
                cp16(dst + dsw[l], a2 + (size_t)l * 16 * 32);
                cp16(dst + CH_BYTES + dsw[l], b2 + (size_t)l * 16 * 32);
            }
            CP_COMMIT();
        }

        const uint32_t Ab = sb + (kc & 1) * STAGE_BYTES;
        const uint32_t Bb = Ab + CH_BYTES;
#pragma unroll
        for (int k32 = 0; k32 < 4; k32++) {
            const uint32_t cb = k32 * 32;
            uint32_t af[4][4], bf[4][4];
#pragma unroll
            for (int mf = 0; mf < 4; mf++)
                ldmx4(af[mf], Ab + (a_off[mf] ^ cb));
#pragma unroll
            for (int q = 0; q < 4; q++)
                ldmx4(bf[q], Bb + (b_off[q] ^ cb));
#pragma unroll
            for (int mf = 0; mf < 4; mf++)
#pragma unroll
                for (int q = 0; q < 4; q++) {
                    mma_fp8(c[mf][q * 2 + 0], af[mf], &bf[q][0]);
                    mma_fp8(c[mf][q * 2 + 1], af[mf], &bf[q][2]);
                }
        }
    }

    // ---- epilogue: exp in place, positives, row sums, (off-diag) col sums ----
    const int lr0 = wm * 64 + (lane >> 2);       // + mf*16 + h*8  (local row)
    const int lc0 = wn * 64 + (lane & 3) * 2;    // + nf*8 + e     (local col)
    const bool pos_tile = (ct == (rt ^ 32));

#pragma unroll
    for (int mf = 0; mf < 4; mf++)
#pragma unroll
        for (int nf = 0; nf < 8; nf++)
#pragma unroll
            for (int h = 0; h < 2; h++)
#pragma unroll
                for (int e = 0; e < 2; e++) {
                    const int lr = lr0 + mf * 16 + h * 8;
                    const int lc = lc0 + nf * 8 + e;
                    const bool eq = (lr == lc);
                    const float sv = c[mf][nf][h * 2 + e];
                    if (pos_tile && eq) {
                        g_pos[row_base + lr] = sv;
                        g_pos[col_base + lc] = sv;
                    }
                    c[mf][nf][h * 2 + e] = (diag && eq) ? 0.0f : ex2f(sv * EXP_SCALE);
                }

    // row sums (lanes sharing a row: bits 0-1)
#pragma unroll
    for (int mf = 0; mf < 4; mf++)
#pragma unroll
        for (int h = 0; h < 2; h++) {
            float v = 0.0f;
#pragma unroll
            for (int nf = 0; nf < 8; nf++)
                v += c[mf][nf][h * 2 + 0] + c[mf][nf][h * 2 + 1];
            v += __shfl_xor_sync(0xffffffffu, v, 1);
            v += __shfl_xor_sync(0xffffffffu, v, 2);
            if ((lane & 3) == 0)
                atomicAdd(&g_S[row_base + lr0 + mf * 16 + h * 8], v);
        }

    // col sums (transpose contribution; lanes sharing a col: bits 2-4)
    if (!diag) {
#pragma unroll
        for (int nf = 0; nf < 8; nf++)
#pragma unroll
            for (int e = 0; e < 2; e++) {
                float v = 0.0f;
#pragma unroll
                for (int mf = 0; mf < 4; mf++)
                    v += c[mf][nf][e] + c[mf][nf][2 + e];
                v += __shfl_xor_sync(0xffffffffu, v, 4);
                v += __shfl_xor_sync(0xffffffffu, v, 8);
                v += __shfl_xor_sync(0xffffffffu, v, 16);
                if (lane < 4)
                    atomicAdd(&g_S[col_base + lc0 + nf * 8 + e], v);
            }
    }

    // ---- fused final loss: last CTA reduces g_S / g_pos ----
    __threadfence();
    __shared__ unsigned int s_last;
    __syncthreads();
    if (tid == 0) s_last = atomicAdd(&g_cnt, 1u);
    __syncthreads();
    if (s_last == NTILES - 1) {
        __threadfence();
        float acc = 0.0f;
        for (int i = tid; i < NROWS; i += THREADS)
            acc += -POS_SCALE * g_pos[i] + logf(g_S[i]);
#pragma unroll
        for (int m = 16; m; m >>= 1) acc += __shfl_xor_sync(0xffffffffu, acc, m);
        __shared__ float red[4];
        if (lane == 0) red[wid] = acc;
        __syncthreads();
        if (tid == 0) {
            float v = red[0] + red[1] + red[2] + red[3];
            out[0] = v * (1.0f / NROWS);
            g_cnt = 0;   // reset for next graph replay
        }
    }
}

extern "C" void kernel_launch(void* const* d_in, const int* in_sizes, int n_in,
                              void* d_out, int out_size) {
    const float* a = (const float*)d_in[0];
    const float* b = (const float*)d_in[1];
    (void)in_sizes; (void)n_in; (void)out_size;

    cudaFuncSetAttribute(gemm_kernel, cudaFuncAttributeMaxDynamicSharedMemorySize, SMEM_TOTAL);

    norm_kernel<<<NROWS / 8, 256>>>(a, b);
    gemm_kernel<<<NTILES, THREADS, SMEM_TOTAL>>>((float*)d_out);
}

// round 14
// speedup vs baseline: 1.2569x; 1.2569x over previous
#include <cuda_runtime.h>
#include <cuda_bf16.h>
#include <math.h>
#include <stdint.h>

// ConLoss (NT-Xent): z = normalize(concat(h1,h2)) [8192,512]; sim = z z^T; T=0.5
// loss_i = -2*sim[i,i^4096] + log(sum_{j!=i} exp(2*sim_ij)); out = mean.
// Round 14: single fused persistent kernel. Phase 0 normalize (warp/row) ->
// grid barrier (296 CTAs co-resident by construction) -> R12 dynamic-stealing
// fp8 mma.sync tile loop (upper-triangle symmetry) -> last-CTA loss.
// Note: legacy mma.sync is MAC-width-capped (~512 MAC/cyc/SM); GEMM is at
// ~96% of that wall, so this round only removes launch/phase overhead.

#define NROWS 8192
#define HALF  4096
#define D     512

#define THREADS 256
#define NCTA 296                      // 2 per SM x 148 SMs (all co-resident)
#define BT 128                        // tile dim
#define NT (NROWS / BT)               // 64
#define NTILES (NT * (NT + 1) / 2)    // 2080
#define NKC 4                         // k chunks of 128

#define CH_BYTES (BT * 128)           // 16 KB per operand chunk
#define STAGE_BYTES (2 * CH_BYTES)    // 32 KB (A+B)
#define SMEM_TOTAL (2 * STAGE_BYTES)  // 64 KB

// exp(2*sim) = 2^(acc * 2*log2e/256), acc = 256*sim (z scaled by 16)
#define EXP_SCALE 0.0112710550f
#define POS_SCALE 0.0078125f          // 2/256

__device__ __align__(16) uint8_t g_z8[NROWS * D];
__device__ float g_S[NROWS];
__device__ float g_pos[NROWS];
__device__ unsigned int g_cnt = 0;
__device__ unsigned int g_sync = 0;
__device__ unsigned int g_tile = 0;

// ---------------- helpers ----------------
__device__ __forceinline__ uint32_t smem_u32(const void* p) {
    uint32_t a;
    asm("{ .reg .u64 t; cvta.to.shared.u64 t, %1; cvt.u32.u64 %0, t; }" : "=r"(a) : "l"(p));
    return a;
}
__device__ __forceinline__ uint32_t SWZ(uint32_t off) {   // SW128 swizzle
    return off ^ ((off >> 3) & 0x70);
}
__device__ __forceinline__ void cp16(uint32_t dst, const void* src) {
    asm volatile("cp.async.cg.shared.global [%0], [%1], 16;" :: "r"(dst), "l"(src));
}
#define CP_COMMIT() asm volatile("cp.async.commit_group;" ::: "memory")
#define CP_WAIT(n)  asm volatile("cp.async.wait_group %0;" :: "n"(n) : "memory")

__device__ __forceinline__ void ldmx4(uint32_t* r, uint32_t addr) {
    asm volatile("ldmatrix.sync.aligned.m8n8.x4.shared.b16 {%0,%1,%2,%3}, [%4];"
                 : "=r"(r[0]), "=r"(r[1]), "=r"(r[2]), "=r"(r[3]) : "r"(addr));
}
__device__ __forceinline__ void mma_fp8(float* c, const uint32_t* a, const uint32_t* b) {
    asm volatile("mma.sync.aligned.m16n8k32.row.col.f32.e4m3.e4m3.f32 "
                 "{%0,%1,%2,%3}, {%4,%5,%6,%7}, {%8,%9}, {%0,%1,%2,%3};"
                 : "+f"(c[0]), "+f"(c[1]), "+f"(c[2]), "+f"(c[3])
                 : "r"(a[0]), "r"(a[1]), "r"(a[2]), "r"(a[3]), "r"(b[0]), "r"(b[1]));
}
__device__ __forceinline__ float ex2f(float x) {
    float y;
    asm("ex2.approx.f32 %0, %1;" : "=f"(y) : "f"(x));
    return y;
}
__device__ __forceinline__ uint32_t pack_e4m3(float f0, float f1, float f2, float f3) {
    uint16_t lo, hi;
    asm("cvt.rn.satfinite.e4m3x2.f32 %0, %1, %2;" : "=h"(lo) : "f"(f1), "f"(f0));
    asm("cvt.rn.satfinite.e4m3x2.f32 %0, %1, %2;" : "=h"(hi) : "f"(f3), "f"(f2));
    return (uint32_t)lo | ((uint32_t)hi << 16);
}

// decode flat upper-triangle index -> (rt, ct), ct >= rt
__device__ __forceinline__ void decode_tile(int flat, int& rt, int& ct) {
    int r = (int)((2 * NT + 1 - sqrtf((float)((2 * NT + 1) * (2 * NT + 1) - 8 * flat))) * 0.5f);
    while (r * (2 * NT + 1 - r) / 2 > flat) r--;
    while ((r + 1) * (2 * NT - r) / 2 <= flat) r++;
    rt = r;
    ct = r + (flat - r * (2 * NT + 1 - r) / 2);
}

// ---------------- the fused kernel ----------------
__global__ __launch_bounds__(THREADS, 2) void fused_kernel(
    const float* __restrict__ ha, const float* __restrict__ hb,
    float* __restrict__ out) {
    extern __shared__ __align__(1024) char smem[];
    const uint32_t sb = smem_u32(smem);
    const int tid  = threadIdx.x;
    const int wid  = tid >> 5;
    const int lane = tid & 31;

    // ======== phase 0: normalize rows -> e4m3 (x16), zero g_S ========
    {
        const int gt = blockIdx.x * THREADS + tid;
        if (gt < NROWS) g_S[gt] = 0.0f;
        if (gt == 0) g_tile = NCTA;      // seed dynamic tile counter

        const int gw0 = gt >> 5;         // global warp id
        for (int gw = gw0; gw < NROWS; gw += NCTA * (THREADS / 32)) {
            const float* src = (gw < HALF) ? (ha + (size_t)gw * D)
                                           : (hb + (size_t)(gw - HALF) * D);
            const float4* s4 = (const float4*)src;
            float4 v[4];
            float ss = 0.0f;
#pragma unroll
            for (int l = 0; l < 4; l++) {
                v[l] = s4[lane + l * 32];
                ss += v[l].x * v[l].x + v[l].y * v[l].y + v[l].z * v[l].z + v[l].w * v[l].w;
            }
#pragma unroll
            for (int m = 16; m; m >>= 1) ss += __shfl_xor_sync(0xffffffffu, ss, m);
            float inv = 16.0f / fmaxf(sqrtf(ss), 1e-8f);
            uint32_t* d32 = (uint32_t*)(g_z8 + (size_t)gw * D);
#pragma unroll
            for (int l = 0; l < 4; l++) {
                float4 w = v[l];
                d32[lane + 32 * l] = pack_e4m3(w.x * inv, w.y * inv, w.z * inv, w.w * inv);
            }
        }
    }

    // ======== grid barrier (all NCTA CTAs are co-resident) ========
    __syncthreads();
    if (tid == 0) {
        __threadfence();
        atomicAdd(&g_sync, 1u);
        unsigned int v;
        do {
            asm volatile("ld.acquire.gpu.u32 %0, [%1];" : "=r"(v) : "l"(&g_sync));
            if (v < NCTA) __nanosleep(64);
        } while (v < NCTA);
    }
    __syncthreads();

    // ======== phase 1: upper-triangle tile GEMM with dynamic stealing ========
    const int wm = wid & 3;        // row warp: 32 rows
    const int wn = wid >> 2;       // col warp: 64 cols

    // hoisted cp.async addressing
    const int ld_row = tid >> 3;          // 0..31
    const int ld_g   = tid & 7;           // 0..7 (16B groups)
    uint32_t dsw[4];
#pragma unroll
    for (int l = 0; l < 4; l++)
        dsw[l] = SWZ((ld_row + 32 * l) * 128 + ld_g * 16);

    // hoisted ldmatrix addressing (XOR-advance along k: offsets in bits 4-6)
    const int a_row0 = wm * 32 + (lane & 15);
    const uint32_t a_off0 = SWZ(a_row0 * 128 + (lane >> 4) * 16);
    const uint32_t a_off1 = SWZ((a_row0 + 16) * 128 + (lane >> 4) * 16);
    const int b_row0 = wn * 64 + (lane & 7) + ((lane & 16) ? 8 : 0);
    uint32_t b_off[4];
#pragma unroll
    for (int q = 0; q < 4; q++)
        b_off[q] = SWZ((b_row0 + q * 16) * 128 + ((lane & 8) ? 16 : 0));

    // epilogue local indices
    const int lr0 = wm * 32 + (lane >> 2);      // + mf*16 + h*8
    const int lc0 = wn * 64 + (lane & 3) * 2;   // + nf*8 + e

    const uint4* Z4 = (const uint4*)g_z8;       // 32 uint4 per row

    __shared__ unsigned int s_nxt;

    int cur = blockIdx.x;                       // first tile = bid
    int rt, ct;
    decode_tile(cur, rt, ct);
    int row_base = rt * BT, col_base = ct * BT;

    // prologue: chunk 0 of first tile
    {
        const uint4* as = Z4 + (size_t)(row_base + ld_row) * 32 + ld_g;
        const uint4* bs = Z4 + (size_t)(col_base + ld_row) * 32 + ld_g;
#pragma unroll
        for (int l = 0; l < 4; l++) {
            cp16(sb + dsw[l], as + (size_t)l * 32 * 32);
            cp16(sb + CH_BYTES + dsw[l], bs + (size_t)l * 32 * 32);
        }
        CP_COMMIT();
    }

    int st = 0;   // stage of current chunk

    while (cur < NTILES) {
        if (tid == 0) s_nxt = atomicAdd(&g_tile, 1u);

        float c[2][8][4];
#pragma unroll
        for (int mf = 0; mf < 2; mf++)
#pragma unroll
            for (int nf = 0; nf < 8; nf++)
#pragma unroll
                for (int e = 0; e < 4; e++) c[mf][nf][e] = 0.0f;

        int nxt = 0, nrt = 0, nct = 0;
        const uint4* as = Z4 + (size_t)(row_base + ld_row) * 32 + ld_g;
        const uint4* bs = Z4 + (size_t)(col_base + ld_row) * 32 + ld_g;

#pragma unroll
        for (int kc = 0; kc < NKC; kc++) {
            CP_WAIT(0);             // this chunk resident
            __syncthreads();        // publish + all warps done w/ other stage
            if (kc == 0) {
                nxt = (int)s_nxt;
                if (nxt < NTILES) decode_tile(nxt, nrt, nct);
            }
            // prefetch next chunk into the other stage
            const uint32_t dst = sb + (st ^ 1) * STAGE_BYTES;
            if (kc < NKC - 1) {
                const uint4* a2 = as + (size_t)(kc + 1) * 8;
                const uint4* b2 = bs + (size_t)(kc + 1) * 8;
#pragma unroll
                for (int l = 0; l < 4; l++) {
                    cp16(dst + dsw[l], a2 + (size_t)l * 32 * 32);
                    cp16(dst + CH_BYTES + dsw[l], b2 + (size_t)l * 32 * 32);
                }
                CP_COMMIT();
            } else if (nxt < NTILES) {   // next tile's chunk 0
                const uint4* a2 = Z4 + (size_t)(nrt * BT + ld_row) * 32 + ld_g;
                const uint4* b2 = Z4 + (size_t)(nct * BT + ld_row) * 32 + ld_g;
#pragma unroll
                for (int l = 0; l < 4; l++) {
                    cp16(dst + dsw[l], a2 + (size_t)l * 32 * 32);
                    cp16(dst + CH_BYTES + dsw[l], b2 + (size_t)l * 32 * 32);
                }
                CP_COMMIT();
            }

            const uint32_t Ab = sb + st * STAGE_BYTES;
            const uint32_t Bb = Ab + CH_BYTES;
#pragma unroll
            for (int k32 = 0; k32 < 4; k32++) {
                const uint32_t cb = k32 * 32;
                uint32_t af[2][4];
                ldmx4(af[0], Ab + (a_off0 ^ cb));
                ldmx4(af[1], Ab + (a_off1 ^ cb));
#pragma unroll
                for (int q = 0; q < 4; q++) {
                    uint32_t bf[4];
                    ldmx4(bf, Bb + (b_off[q] ^ cb));
                    mma_fp8(c[0][q * 2 + 0], af[0], &bf[0]);
                    mma_fp8(c[0][q * 2 + 1], af[0], &bf[2]);
                    mma_fp8(c[1][q * 2 + 0], af[1], &bf[0]);
                    mma_fp8(c[1][q * 2 + 1], af[1], &bf[2]);
                }
            }
            st ^= 1;
        }

        // ---- epilogue (overlaps next tile's chunk-0 load) ----
        const bool diag = (rt == ct);
        const bool pos_tile = (ct == (rt ^ 32));

#pragma unroll
        for (int mf = 0; mf < 2; mf++)
#pragma unroll
            for (int nf = 0; nf < 8; nf++)
#pragma unroll
                for (int h = 0; h < 2; h++)
#pragma unroll
                    for (int e = 0; e < 2; e++) {
                        const int lr = lr0 + mf * 16 + h * 8;
                        const int lc = lc0 + nf * 8 + e;
                        const bool eq = (lr == lc);
                        const float sv = c[mf][nf][h * 2 + e];
                        if (pos_tile && eq) {
                            g_pos[row_base + lr] = sv;
                            g_pos[col_base + lc] = sv;
                        }
                        c[mf][nf][h * 2 + e] = (diag && eq) ? 0.0f : ex2f(sv * EXP_SCALE);
                    }

        // row sums (lanes sharing a row: bits 0-1)
#pragma unroll
        for (int mf = 0; mf < 2; mf++)
#pragma unroll
            for (int h = 0; h < 2; h++) {
                float v = 0.0f;
#pragma unroll
                for (int nf = 0; nf < 8; nf++)
                    v += c[mf][nf][h * 2 + 0] + c[mf][nf][h * 2 + 1];
                v += __shfl_xor_sync(0xffffffffu, v, 1);
                v += __shfl_xor_sync(0xffffffffu, v, 2);
                if ((lane & 3) == 0)
                    atomicAdd(&g_S[row_base + lr0 + mf * 16 + h * 8], v);
            }

        // col sums (transpose contribution; lanes sharing a col: bits 2-4)
        if (!diag) {
#pragma unroll
            for (int nf = 0; nf < 8; nf++)
#pragma unroll
                for (int e = 0; e < 2; e++) {
                    float v = c[0][nf][e] + c[0][nf][2 + e] + c[1][nf][e] + c[1][nf][2 + e];
                    v += __shfl_xor_sync(0xffffffffu, v, 4);
                    v += __shfl_xor_sync(0xffffffffu, v, 8);
                    v += __shfl_xor_sync(0xffffffffu, v, 16);
                    if (lane < 4)
                        atomicAdd(&g_S[col_base + lc0 + nf * 8 + e], v);
                }
        }

        cur = nxt; rt = nrt; ct = nct;
        row_base = rt * BT; col_base = ct * BT;
    }

    // ======== fused final loss: last CTA reduces g_S / g_pos ========
    __threadfence();
    __shared__ unsigned int s_last;
    __syncthreads();
    if (tid == 0) s_last = atomicAdd(&g_cnt, 1u);
    __syncthreads();
    if (s_last == NCTA - 1) {
        __threadfence();
        float acc = 0.0f;
        for (int i = tid; i < NROWS; i += THREADS)
            acc += -POS_SCALE * g_pos[i] + logf(g_S[i]);
#pragma unroll
        for (int m = 16; m; m >>= 1) acc += __shfl_xor_sync(0xffffffffu, acc, m);
        __shared__ float red[8];
        if (lane == 0) red[wid] = acc;
        __syncthreads();
        if (tid == 0) {
            float v = 0.0f;
#pragma unroll
            for (int w = 0; w < 8; w++) v += red[w];
            out[0] = v * (1.0f / NROWS);
            g_cnt = 0;    // reset counters for next graph replay
            g_sync = 0;
        }
    }
}

extern "C" void kernel_launch(void* const* d_in, const int* in_sizes, int n_in,
                              void* d_out, int out_size) {
    const float* a = (const float*)d_in[0];
    const float* b = (const float*)d_in[1];
    (void)in_sizes; (void)n_in; (void)out_size;

    cudaFuncSetAttribute(fused_kernel, cudaFuncAttributeMaxDynamicSharedMemorySize, SMEM_TOTAL);
    fused_kernel<<<NCTA, THREADS, SMEM_TOTAL>>>(a, b, (float*)d_out);
}

// round 16
// speedup vs baseline: 1.4039x; 1.1169x over previous
#include <cuda_runtime.h>
#include <cuda_fp16.h>
#include <math.h>
#include <stdint.h>

// ConLoss (NT-Xent): z = normalize(concat(h1,h2)) [8192,512]; sim = z z^T; T=0.5
// loss_i = -2*sim[i,i^4096] + log(sum_{j!=i} exp(2*sim_ij)); out = mean.
// Round 15: e4m3 mma.sync with F16 ACCUMULATORS (32 regs instead of 64) +
// explicit double-buffered ldmatrix fragments to hide LDSM->MMA latency.
// Upper-triangle symmetry, 2-stage cp.async ring, 2 CTAs/SM, last-CTA loss.

#define NROWS 8192
#define HALF  4096
#define D     512

#define THREADS 256
#define BT 128                        // tile dim
#define NT (NROWS / BT)               // 64
#define NTILES (NT * (NT + 1) / 2)    // 2080
#define NKC 4                         // k chunks of 128

#define CH_BYTES (BT * 128)           // 16 KB per operand chunk
#define STAGE_BYTES (2 * CH_BYTES)    // 32 KB (A+B)
#define SMEM_TOTAL (2 * STAGE_BYTES)  // 64 KB

// exp(2*sim) = 2^(acc * 2*log2e/256), acc = 256*sim (z scaled by 16)
#define EXP_SCALE 0.0112710550f
#define POS_SCALE 0.0078125f          // 2/256

__device__ __align__(16) uint8_t g_z8[NROWS * D];
__device__ float g_S[NROWS];
__device__ float g_pos[NROWS];
__device__ unsigned int g_cnt = 0;

// ---------------- helpers ----------------
__device__ __forceinline__ uint32_t smem_u32(const void* p) {
    uint32_t a;
    asm("{ .reg .u64 t; cvta.to.shared.u64 t, %1; cvt.u32.u64 %0, t; }" : "=r"(a) : "l"(p));
    return a;
}
__device__ __forceinline__ uint32_t SWZ(uint32_t off) {   // SW128 swizzle
    return off ^ ((off >> 3) & 0x70);
}
__device__ __forceinline__ void cp16(uint32_t dst, const void* src) {
    asm volatile("cp.async.cg.shared.global [%0], [%1], 16;" :: "r"(dst), "l"(src));
}
#define CP_COMMIT() asm volatile("cp.async.commit_group;" ::: "memory")
#define CP_WAIT(n)  asm volatile("cp.async.wait_group %0;" :: "n"(n) : "memory")

__device__ __forceinline__ void ldmx4(uint32_t* r, uint32_t addr) {
    asm volatile("ldmatrix.sync.aligned.m8n8.x4.shared.b16 {%0,%1,%2,%3}, [%4];"
                 : "=r"(r[0]), "=r"(r[1]), "=r"(r[2]), "=r"(r[3]) : "r"(addr));
}
// fp8 x fp8 -> f16 accumulators (2 regs = 4 halves per fragment)
__device__ __forceinline__ void mma_fp8h(uint32_t* c, const uint32_t* a, const uint32_t* b) {
    asm volatile("mma.sync.aligned.m16n8k32.row.col.f16.e4m3.e4m3.f16 "
                 "{%0,%1}, {%2,%3,%4,%5}, {%6,%7}, {%0,%1};"
                 : "+r"(c[0]), "+r"(c[1])
                 : "r"(a[0]), "r"(a[1]), "r"(a[2]), "r"(a[3]), "r"(b[0]), "r"(b[1]));
}
__device__ __forceinline__ float ex2f(float x) {
    float y;
    asm("ex2.approx.f32 %0, %1;" : "=f"(y) : "f"(x));
    return y;
}
__device__ __forceinline__ uint32_t pack_e4m3(float f0, float f1, float f2, float f3) {
    uint16_t lo, hi;
    asm("cvt.rn.satfinite.e4m3x2.f32 %0, %1, %2;" : "=h"(lo) : "f"(f1), "f"(f0));
    asm("cvt.rn.satfinite.e4m3x2.f32 %0, %1, %2;" : "=h"(hi) : "f"(f3), "f"(f2));
    return (uint32_t)lo | ((uint32_t)hi << 16);
}

// ---------------- kernels ----------------
// One warp per row: normalize, scale by 16, write e4m3. Also zeroes g_S.
__global__ void norm_kernel(const float* __restrict__ a, const float* __restrict__ b) {
    int gt = blockIdx.x * blockDim.x + threadIdx.x;
    if (gt < NROWS) g_S[gt] = 0.0f;
    int gw   = gt >> 5;
    int lane = threadIdx.x & 31;
    if (gw >= NROWS) return;
    const float* src = (gw < HALF) ? (a + (size_t)gw * D) : (b + (size_t)(gw - HALF) * D);
    const float4* s4 = (const float4*)src;
    float4 v[4];
    float ss = 0.0f;
#pragma unroll
    for (int l = 0; l < 4; l++) {
        v[l] = s4[lane + l * 32];
        ss += v[l].x * v[l].x + v[l].y * v[l].y + v[l].z * v[l].z + v[l].w * v[l].w;
    }
#pragma unroll
    for (int m = 16; m; m >>= 1) ss += __shfl_xor_sync(0xffffffffu, ss, m);
    float inv = 16.0f / fmaxf(sqrtf(ss), 1e-8f);
    uint32_t* d32 = (uint32_t*)(g_z8 + (size_t)gw * D);
#pragma unroll
    for (int l = 0; l < 4; l++) {
        float4 w = v[l];
        d32[lane + 32 * l] = pack_e4m3(w.x * inv, w.y * inv, w.z * inv, w.w * inv);
    }
}

// One CTA per upper-triangle tile (rt, ct), ct >= rt. 256 thr = 8 warps (4x2),
// warp tile 32x64, f16 accumulators.
__global__ __launch_bounds__(THREADS, 2) void gemm_kernel(float* __restrict__ out) {
    extern __shared__ __align__(1024) char smem[];
    const uint32_t sb = smem_u32(smem);
    const int tid  = threadIdx.x;
    const int wid  = tid >> 5;
    const int lane = tid & 31;
    const int wm = wid & 3;        // row warp: 32 rows
    const int wn = wid >> 2;       // col warp: 64 cols

    // decode flat tile index -> (rt, ct), ct >= rt
    const int flat = blockIdx.x;
    int rt = (int)((2 * NT + 1 - sqrtf((float)((2 * NT + 1) * (2 * NT + 1) - 8 * flat))) * 0.5f);
    while (rt * (2 * NT + 1 - rt) / 2 > flat) rt--;
    while ((rt + 1) * (2 * NT - rt) / 2 <= flat) rt++;
    const int ct = rt + (flat - rt * (2 * NT + 1 - rt) / 2);
    const int row_base = rt * BT;
    const int col_base = ct * BT;
    const bool diag = (rt == ct);

    const uint4* Z4 = (const uint4*)g_z8;   // 32 uint4 per row

    // hoisted cp.async addressing
    const int ld_row = tid >> 3;          // 0..31
    const int ld_g   = tid & 7;
    uint32_t dsw[4];
#pragma unroll
    for (int l = 0; l < 4; l++)
        dsw[l] = SWZ((ld_row + 32 * l) * 128 + ld_g * 16);
    const uint4* as0 = Z4 + (size_t)(row_base + ld_row) * 32 + ld_g;
    const uint4* bs0 = Z4 + (size_t)(col_base + ld_row) * 32 + ld_g;

    // prologue: chunk 0
#pragma unroll
    for (int l = 0; l < 4; l++) {
        cp16(sb + dsw[l], as0 + (size_t)l * 32 * 32);
        cp16(sb + CH_BYTES + dsw[l], bs0 + (size_t)l * 32 * 32);
    }
    CP_COMMIT();

    // ldmatrix lane addressing (XOR-advance along k: k-offsets in bits 4-6)
    const int a_row0 = wm * 32 + (lane & 15);
    const uint32_t a_off0 = SWZ(a_row0 * 128 + (lane >> 4) * 16);
    const uint32_t a_off1 = SWZ((a_row0 + 16) * 128 + (lane >> 4) * 16);
    const int b_row0 = wn * 64 + (lane & 7) + ((lane & 16) ? 8 : 0);
    uint32_t b_off[4];
#pragma unroll
    for (int q = 0; q < 4; q++)
        b_off[q] = SWZ((b_row0 + q * 16) * 128 + ((lane & 8) ? 16 : 0));

    // f16 accumulators: c[mf][nf][h] is a half2 (cols e=0,1) for row +h*8
    uint32_t c[2][8][2];
#pragma unroll
    for (int mf = 0; mf < 2; mf++)
#pragma unroll
        for (int nf = 0; nf < 8; nf++) { c[mf][nf][0] = 0u; c[mf][nf][1] = 0u; }

    // double-buffered fragments
    uint32_t af[2][2][4], bf[2][4][4];

#pragma unroll
    for (int kc = 0; kc < NKC; kc++) {
        CP_WAIT(0);            // chunk kc resident
        __syncthreads();       // publish + all warps done with the other stage
        if (kc + 1 < NKC) {    // prefetch next chunk into freed stage
            const uint32_t dst = sb + ((kc + 1) & 1) * STAGE_BYTES;
            const uint4* a2 = as0 + (size_t)(kc + 1) * 8;
            const uint4* b2 = bs0 + (size_t)(kc + 1) * 8;
#pragma unroll
            for (int l = 0; l < 4; l++) {
                cp16(dst + dsw[l], a2 + (size_t)l * 32 * 32);
                cp16(dst + CH_BYTES + dsw[l], b2 + (size_t)l * 32 * 32);
            }
            CP_COMMIT();
        }

        const uint32_t Ab = sb + (kc & 1) * STAGE_BYTES;
        const uint32_t Bb = Ab + CH_BYTES;

        // preload fragments for k32=0
        ldmx4(af[0][0], Ab + a_off0);
        ldmx4(af[0][1], Ab + a_off1);
#pragma unroll
        for (int q = 0; q < 4; q++)
            ldmx4(bf[0][q], Bb + b_off[q]);

#pragma unroll
        for (int k32 = 0; k32 < 4; k32++) {
            const int cur = k32 & 1;
            if (k32 < 3) {               // prefetch next k32's fragments
                const uint32_t cb = (k32 + 1) * 32;
                const int nb = cur ^ 1;
                ldmx4(af[nb][0], Ab + (a_off0 ^ cb));
                ldmx4(af[nb][1], Ab + (a_off1 ^ cb));
#pragma unroll
                for (int q = 0; q < 4; q++)
                    ldmx4(bf[nb][q], Bb + (b_off[q] ^ cb));
            }
#pragma unroll
            for (int mf = 0; mf < 2; mf++)
#pragma unroll
                for (int q = 0; q < 4; q++) {
                    mma_fp8h(c[mf][q * 2 + 0], af[cur][mf], &bf[cur][q][0]);
                    mma_fp8h(c[mf][q * 2 + 1], af[cur][mf], &bf[cur][q][2]);
                }
        }
    }

    // ---- epilogue: exp in place (half2), positives, row/col sums ----
    const int lr0 = wm * 32 + (lane >> 2);       // + mf*16 + h*8  (local row)
    const int lc0 = wn * 64 + (lane & 3) * 2;    // + nf*8 (+e)    (local col)
    const bool pos_tile = (ct == (rt ^ 32));

#pragma unroll
    for (int mf = 0; mf < 2; mf++)
#pragma unroll
        for (int nf = 0; nf < 8; nf++)
#pragma unroll
            for (int h = 0; h < 2; h++) {
                const int lr = lr0 + mf * 16 + h * 8;
                const int lc = lc0 + nf * 8;
                float2 f = __half22float2(*(const __half2*)&c[mf][nf][h]);
                if (pos_tile) {
                    if (lr == lc)     { g_pos[row_base + lr] = f.x; g_pos[col_base + lc] = f.x; }
                    if (lr == lc + 1) { g_pos[row_base + lr] = f.y; g_pos[col_base + lc + 1] = f.y; }
                }
                float e0 = (diag && lr == lc)     ? 0.0f : ex2f(f.x * EXP_SCALE);
                float e1 = (diag && lr == lc + 1) ? 0.0f : ex2f(f.y * EXP_SCALE);
                *(__half2*)&c[mf][nf][h] = __floats2half2_rn(e0, e1);
            }

    // row sums: half2 adds over nf, then float; lanes sharing a row: bits 0-1
#pragma unroll
    for (int mf = 0; mf < 2; mf++)
#pragma unroll
        for (int h = 0; h < 2; h++) {
            __half2 s = __floats2half2_rn(0.0f, 0.0f);
#pragma unroll
            for (int nf = 0; nf < 8; nf++)
                s = __hadd2(s, *(const __half2*)&c[mf][nf][h]);
            float2 fs = __half22float2(s);
            float v = fs.x + fs.y;
            v += __shfl_xor_sync(0xffffffffu, v, 1);
            v += __shfl_xor_sync(0xffffffffu, v, 2);
            if ((lane & 3) == 0)
                atomicAdd(&g_S[row_base + lr0 + mf * 16 + h * 8], v);
        }

    // col sums (transpose contribution; lanes sharing a col: bits 2-4)
    if (!diag) {
#pragma unroll
        for (int nf = 0; nf < 8; nf++) {
            __half2 s = __floats2half2_rn(0.0f, 0.0f);
#pragma unroll
            for (int mf = 0; mf < 2; mf++)
#pragma unroll
                for (int h = 0; h < 2; h++)
                    s = __hadd2(s, *(const __half2*)&c[mf][nf][h]);
            float2 fs = __half22float2(s);
#pragma unroll
            for (int e = 0; e < 2; e++) {
                float v = (e == 0) ? fs.x : fs.y;
                v += __shfl_xor_sync(0xffffffffu, v, 4);
                v += __shfl_xor_sync(0xffffffffu, v, 8);
                v += __shfl_xor_sync(0xffffffffu, v, 16);
                if (lane < 4)
                    atomicAdd(&g_S[col_base + lc0 + nf * 8 + e], v);
            }
        }
    }

    // ---- fused final loss: last CTA reduces g_S / g_pos ----
    __threadfence();
    __shared__ unsigned int s_last;
    __syncthreads();
    if (tid == 0) s_last = atomicAdd(&g_cnt, 1u);
    __syncthreads();
    if (s_last == NTILES - 1) {
        __threadfence();
        float acc = 0.0f;
        for (int i = tid; i < NROWS; i += THREADS)
            acc += -POS_SCALE * g_pos[i] + logf(g_S[i]);
#pragma unroll
        for (int m = 16; m; m >>= 1) acc += __shfl_xor_sync(0xffffffffu, acc, m);
        __shared__ float red[8];
        if (lane == 0) red[wid] = acc;
        __syncthreads();
        if (tid == 0) {
            float v = 0.0f;
#pragma unroll
            for (int w = 0; w < 8; w++) v += red[w];
            out[0] = v * (1.0f / NROWS);
            g_cnt = 0;   // reset for next graph replay
        }
    }
}

extern "C" void kernel_launch(void* const* d_in, const int* in_sizes, int n_in,
                              void* d_out, int out_size) {
    const float* a = (const float*)d_in[0];
    const float* b = (const float*)d_in[1];
    (void)in_sizes; (void)n_in; (void)out_size;

    cudaFuncSetAttribute(gemm_kernel, cudaFuncAttributeMaxDynamicSharedMemorySize, SMEM_TOTAL);

    norm_kernel<<<NROWS / 8, 256>>>(a, b);
    gemm_kernel<<<NTILES, THREADS, SMEM_TOTAL>>>((float*)d_out);
}